// round 5
// baseline (speedup 1.0000x reference)
#include <cuda_runtime.h>
#include <cuda_bf16.h>
#include <math.h>
#include <stdint.h>

// Problem shapes (fixed)
#define BB 64
#define TT 512
#define DD 1024
#define UU 128
#define MM (BB * TT)

#define GBM 128
#define GBK 16

// Scratch (no cudaMalloc allowed)
__device__ float g_logits[MM * UU];   // GEMM output
__device__ float g_hist[MM * UU];     // viterbi state history (t>=1)
__device__ int   g_flags[4 * BB];     // per (chunk, batch) ready flags

__global__ void reset_kernel()
{
    g_flags[threadIdx.x] = 0;
}

// ---------------------------------------------------------------------------
// ordered-int argmax helpers (exact, first-index tie rule)
// ---------------------------------------------------------------------------
__device__ __forceinline__ unsigned fkey(float f)
{
    const unsigned b = __float_as_uint(f);
    return b ^ ((unsigned)(((int)b) >> 31) | 0x80000000u);
}
__device__ __forceinline__ unsigned redux_max_u32(unsigned v)
{
    unsigned r;
    asm("redux.sync.max.u32 %0, %1, 0xffffffff;" : "=r"(r) : "r"(v));
    return r;
}
__device__ __forceinline__ unsigned redux_min_u32(unsigned v)
{
    unsigned r;
    asm("redux.sync.min.u32 %0, %1, 0xffffffff;" : "=r"(r) : "r"(v));
    return r;
}

// ---------------------------------------------------------------------------
// Fused kernel. Blocks 0..63: viterbi (one per batch).
// Blocks 64..319: GEMM tiles, chunk-major so early chunks of every batch
// are produced first; each tile publishes a ready flag.
// ---------------------------------------------------------------------------
// Padded stride for transposed chain. MUST keep rows 16B-aligned for float4
// loads: 132 floats = 528 bytes (16B multiple). 132 mod 32 = 4 de-stripes the
// transpose STS (8-way instead of 32-way conflicts).
#define CHT_LD 132

__global__ __launch_bounds__(512, 2)
void fused_kernel(const float* __restrict__ A,
                  const float* __restrict__ W,
                  const float* __restrict__ bias,
                  const float* __restrict__ chain,
                  float* __restrict__ out)
{
    extern __shared__ float sm[];
    const int tid = threadIdx.x;

    if (blockIdx.x >= BB) {
        // =================== GEMM CTA ===================
        float (*As)[GBM] = reinterpret_cast<float (*)[GBM]>(sm);
        float (*Bs)[UU]  = reinterpret_cast<float (*)[UU]>(sm + GBK * GBM);

        const int gblk  = blockIdx.x - BB;   // 0..255
        const int chunk = gblk >> 6;         // 0..3  (t block of 128)
        const int batch = gblk & 63;         // 0..63
        const int row0  = batch * TT + chunk * 128;

        const int arow = tid >> 2;           // 0..127
        const int ak   = (tid & 3) * 4;      // 0,4,8,12
        const int wk   = tid >> 5;           // 0..15
        const int wcol = (tid & 31) * 4;     // 0..124
        const int tx   = tid & 15;           // n block of 8
        const int ty   = tid >> 4;           // 0..31, m block of 4

        float acc[4][8];
        #pragma unroll
        for (int i = 0; i < 4; i++)
            #pragma unroll
            for (int j = 0; j < 8; j++)
                acc[i][j] = 0.0f;

        const float* Arow = A + (size_t)(row0 + arow) * DD + ak;

        for (int k0 = 0; k0 < DD; k0 += GBK) {
            const float4 va = *reinterpret_cast<const float4*>(Arow + k0);
            As[ak + 0][arow] = va.x;
            As[ak + 1][arow] = va.y;
            As[ak + 2][arow] = va.z;
            As[ak + 3][arow] = va.w;
            const float4 vw = *reinterpret_cast<const float4*>(
                &W[(size_t)(k0 + wk) * UU + wcol]);
            *reinterpret_cast<float4*>(&Bs[wk][wcol]) = vw;
            __syncthreads();

            #pragma unroll
            for (int k = 0; k < GBK; k++) {
                float a[4], b[8];
                *reinterpret_cast<float4*>(&a[0]) =
                    *reinterpret_cast<const float4*>(&As[k][ty * 4]);
                *reinterpret_cast<float4*>(&b[0]) =
                    *reinterpret_cast<const float4*>(&Bs[k][tx * 8]);
                *reinterpret_cast<float4*>(&b[4]) =
                    *reinterpret_cast<const float4*>(&Bs[k][tx * 8 + 4]);
                #pragma unroll
                for (int i = 0; i < 4; i++)
                    #pragma unroll
                    for (int j = 0; j < 8; j++)
                        acc[i][j] = fmaf(a[i], b[j], acc[i][j]);
            }
            __syncthreads();
        }

        float bv[8];
        *reinterpret_cast<float4*>(&bv[0]) =
            *reinterpret_cast<const float4*>(&bias[tx * 8]);
        *reinterpret_cast<float4*>(&bv[4]) =
            *reinterpret_cast<const float4*>(&bias[tx * 8 + 4]);

        #pragma unroll
        for (int i = 0; i < 4; i++) {
            const size_t row = (size_t)(row0 + ty * 4 + i);
            float4 o0, o1;
            o0.x = acc[i][0] + bv[0]; o0.y = acc[i][1] + bv[1];
            o0.z = acc[i][2] + bv[2]; o0.w = acc[i][3] + bv[3];
            o1.x = acc[i][4] + bv[4]; o1.y = acc[i][5] + bv[5];
            o1.z = acc[i][6] + bv[6]; o1.w = acc[i][7] + bv[7];
            *reinterpret_cast<float4*>(&g_logits[row * UU + tx * 8])     = o0;
            *reinterpret_cast<float4*>(&g_logits[row * UU + tx * 8 + 4]) = o1;
        }

        __threadfence();
        __syncthreads();
        if (tid == 0)
            atomicExch(&g_flags[chunk * 64 + batch], 1);
        return;
    }

    // =================== Viterbi CTA ===================
    float* chT   = sm;                    // [128][CHT_LD] transposed chain
    float* state = sm + UU * CHT_LD;      // [2][128]  (16B aligned: 128*132*4)

    const int b = blockIdx.x;
    const int u = tid >> 2;               // 0..127
    const int q = tid & 3;                // quarter: u' in [q*32, q*32+32)

    const float* lg = g_logits + (size_t)b * TT * UU;
    float*       hb = g_hist   + (size_t)b * TT * UU;

    // Transposed chain into smem (for backtrace).
    for (int i = tid; i < UU * UU; i += 512) {
        const int r = i >> 7, c = i & 127;
        chT[c * CHT_LD + r] = chain[i];
    }

    // chain column for this (u, quarter) in registers
    float creg[32];
    #pragma unroll
    for (int j = 0; j < 32; j++)
        creg[j] = chain[(size_t)(q * 32 + j) * UU + u];

    // wait for chunk 0 of this batch
    if (tid == 0)
        while (*(volatile int*)&g_flags[b] == 0) { }
    __syncthreads();
    __threadfence();

    if (tid < UU)
        state[tid] = lg[tid];
    __syncthreads();

    int cur = 0;
    float potbuf = lg[UU + u];

    for (int t = 1; t < TT; t++) {
        float pot;
        if ((t & 127) == 0) {
            // chunk boundary: wait for producer, then load fresh
            if (tid == 0)
                while (*(volatile int*)&g_flags[(t >> 7) * 64 + b] == 0) { }
            __syncthreads();
            __threadfence();
            pot = lg[(size_t)t * UU + u];
        } else {
            pot = potbuf;
        }
        if (t + 1 < TT && ((t + 1) & 127) != 0)
            potbuf = lg[(size_t)(t + 1) * UU + u];

        const float* st = state + cur * UU;

        float m0 = -INFINITY, m1 = -INFINITY, m2 = -INFINITY, m3 = -INFINITY;
        #pragma unroll
        for (int j = 0; j < 32; j += 4) {
            const float4 s4 = *reinterpret_cast<const float4*>(&st[q * 32 + j]);
            m0 = fmaxf(m0, s4.x + creg[j + 0]);
            m1 = fmaxf(m1, s4.y + creg[j + 1]);
            m2 = fmaxf(m2, s4.z + creg[j + 2]);
            m3 = fmaxf(m3, s4.w + creg[j + 3]);
        }
        float m = fmaxf(fmaxf(m0, m1), fmaxf(m2, m3));
        m = fmaxf(m, __shfl_xor_sync(0xffffffffu, m, 1));
        m = fmaxf(m, __shfl_xor_sync(0xffffffffu, m, 2));

        const float ns = pot + m;
        if (q == 0)
            state[(cur ^ 1) * UU + u] = ns;   // next-step state (smem)
        else if (q == 1)
            hb[(size_t)t * UU + u] = ns;      // history for backtrace
        cur ^= 1;
        __syncthreads();
    }

    // ---------------- Backtrace: warp 0 only ----------------
    if (tid < 32) {
        const int lane = tid;
        float* o = out + (size_t)b * TT;

        const float4 fs =
            *reinterpret_cast<const float4*>(&state[cur * UU + lane * 4]);
        unsigned k0 = fkey(fs.x), k1 = fkey(fs.y);
        unsigned k2 = fkey(fs.z), k3 = fkey(fs.w);
        unsigned M = redux_max_u32(umax(umax(k0, k1), umax(k2, k3)));
        unsigned idx = 0x7fffffffu;
        if (k3 == M) idx = lane * 4 + 3;
        if (k2 == M) idx = lane * 4 + 2;
        if (k1 == M) idx = lane * 4 + 1;
        if (k0 == M) idx = lane * 4 + 0;
        unsigned tag = redux_min_u32(idx);
        if (lane == 0) o[TT - 1] = (float)tag;

        // state row source: t==0 -> original logits row 0; else history
        const float* row_next = hb + (size_t)(TT - 2) * UU;   // t = TT-2 >= 1
        float4 sb = *reinterpret_cast<const float4*>(&row_next[lane * 4]);
        for (int t = TT - 2; t >= 0; t--) {
            const float4 sv = sb;
            if (t > 0) {
                const float* rp = (t - 1 == 0) ? lg : hb + (size_t)(t - 1) * UU;
                sb = *reinterpret_cast<const float4*>(&rp[lane * 4]);
            }
            const float4 ch = *reinterpret_cast<const float4*>(
                &chT[tag * CHT_LD + lane * 4]);
            k0 = fkey(sv.x + ch.x);
            k1 = fkey(sv.y + ch.y);
            k2 = fkey(sv.z + ch.z);
            k3 = fkey(sv.w + ch.w);
            M = redux_max_u32(umax(umax(k0, k1), umax(k2, k3)));
            idx = 0x7fffffffu;
            if (k3 == M) idx = lane * 4 + 3;
            if (k2 == M) idx = lane * 4 + 2;
            if (k1 == M) idx = lane * 4 + 1;
            if (k0 == M) idx = lane * 4 + 0;
            tag = redux_min_u32(idx);
            if (lane == 0) o[t] = (float)tag;
        }
    }
}

// ---------------------------------------------------------------------------
extern "C" void kernel_launch(void* const* d_in, const int* in_sizes, int n_in,
                              void* d_out, int out_size)
{
    const float* inputs = (const float*)d_in[0];   // (B,T,D)
    const float* kernel = (const float*)d_in[1];   // (D,U)
    const float* bias   = (const float*)d_in[2];   // (U)
    const float* chain  = (const float*)d_in[3];   // (U,U)
    float* out = (float*)d_out;                    // (B,T)

    (void)in_sizes; (void)n_in; (void)out_size;

    reset_kernel<<<1, 4 * BB>>>();

    // dynamic smem: max(viterbi: 128*132 + 256 floats, gemm: 2*16*128 floats)
    const int smem_v = (UU * CHT_LD + 2 * UU) * (int)sizeof(float); // 68608
    cudaFuncSetAttribute(fused_kernel,
                         cudaFuncAttributeMaxDynamicSharedMemorySize,
                         smem_v);
    // grid = 64 viterbi CTAs + 4 chunks * 64 batches GEMM CTAs = 320
    fused_kernel<<<BB + 4 * BB, 512, smem_v>>>(
        inputs, kernel, bias, chain, out);
}

// round 6
// speedup vs baseline: 1.1537x; 1.1537x over previous
#include <cuda_runtime.h>
#include <cuda_bf16.h>
#include <math.h>
#include <stdint.h>

// Problem shapes (fixed)
#define BB 64
#define TT 512
#define DD 1024
#define UU 128
#define MM (BB * TT)

// Scratch (no cudaMalloc allowed)
__device__ float g_logits[MM * UU];   // GEMM output
__device__ float g_hist[MM * UU];     // viterbi state history (t>=1)

// ---------------------------------------------------------------------------
// Kernel 1: logits = X(M,K) @ W(K,U) + bias  (exact fp32 SIMT GEMM, R1 form)
// Tile BM=128, BN=128, BK=16; 256 threads; 8x8 accum per thread.
// ---------------------------------------------------------------------------
#define GBM 128
#define GBK 16

__global__ __launch_bounds__(256, 2)
void gemm_bias_kernel(const float* __restrict__ A,
                      const float* __restrict__ W,
                      const float* __restrict__ bias)
{
    __shared__ float As[GBK][GBM];
    __shared__ float Bs[GBK][UU];

    const int tid  = threadIdx.x;
    const int row0 = blockIdx.x * GBM;

    const int arow = tid >> 2;
    const int ak   = (tid & 3) * 4;
    const int wk   = tid >> 5;
    const int wcol = (tid & 31) * 4;

    const int tx = tid & 15;
    const int ty = tid >> 4;

    float acc[8][8];
    #pragma unroll
    for (int i = 0; i < 8; i++)
        #pragma unroll
        for (int j = 0; j < 8; j++)
            acc[i][j] = 0.0f;

    for (int k0 = 0; k0 < DD; k0 += GBK) {
        #pragma unroll
        for (int i = 0; i < 2; i++) {
            const float4 v = *reinterpret_cast<const float4*>(
                &A[(size_t)(row0 + arow + i * 64) * DD + k0 + ak]);
            As[ak + 0][arow + i * 64] = v.x;
            As[ak + 1][arow + i * 64] = v.y;
            As[ak + 2][arow + i * 64] = v.z;
            As[ak + 3][arow + i * 64] = v.w;
        }
        #pragma unroll
        for (int i = 0; i < 2; i++) {
            const float4 v = *reinterpret_cast<const float4*>(
                &W[(size_t)(k0 + wk + i * 8) * UU + wcol]);
            *reinterpret_cast<float4*>(&Bs[wk + i * 8][wcol]) = v;
        }
        __syncthreads();

        #pragma unroll
        for (int k = 0; k < GBK; k++) {
            float a[8], b[8];
            *reinterpret_cast<float4*>(&a[0]) =
                *reinterpret_cast<const float4*>(&As[k][ty * 8]);
            *reinterpret_cast<float4*>(&a[4]) =
                *reinterpret_cast<const float4*>(&As[k][ty * 8 + 4]);
            *reinterpret_cast<float4*>(&b[0]) =
                *reinterpret_cast<const float4*>(&Bs[k][tx * 8]);
            *reinterpret_cast<float4*>(&b[4]) =
                *reinterpret_cast<const float4*>(&Bs[k][tx * 8 + 4]);
            #pragma unroll
            for (int i = 0; i < 8; i++)
                #pragma unroll
                for (int j = 0; j < 8; j++)
                    acc[i][j] = fmaf(a[i], b[j], acc[i][j]);
        }
        __syncthreads();
    }

    float bv[8];
    *reinterpret_cast<float4*>(&bv[0]) =
        *reinterpret_cast<const float4*>(&bias[tx * 8]);
    *reinterpret_cast<float4*>(&bv[4]) =
        *reinterpret_cast<const float4*>(&bias[tx * 8 + 4]);

    #pragma unroll
    for (int i = 0; i < 8; i++) {
        const size_t row = (size_t)(row0 + ty * 8 + i);
        float4 o0, o1;
        o0.x = acc[i][0] + bv[0]; o0.y = acc[i][1] + bv[1];
        o0.z = acc[i][2] + bv[2]; o0.w = acc[i][3] + bv[3];
        o1.x = acc[i][4] + bv[4]; o1.y = acc[i][5] + bv[5];
        o1.z = acc[i][6] + bv[6]; o1.w = acc[i][7] + bv[7];
        *reinterpret_cast<float4*>(&g_logits[row * UU + tx * 8])     = o0;
        *reinterpret_cast<float4*>(&g_logits[row * UU + tx * 8 + 4]) = o1;
    }
}

// ---------------------------------------------------------------------------
// ordered-int argmax helpers (exact, first-index tie rule)
// ---------------------------------------------------------------------------
__device__ __forceinline__ unsigned fkey(float f)
{
    const unsigned b = __float_as_uint(f);
    return b ^ ((unsigned)(((int)b) >> 31) | 0x80000000u);
}
__device__ __forceinline__ unsigned redux_max_u32(unsigned v)
{
    unsigned r;
    asm("redux.sync.max.u32 %0, %1, 0xffffffff;" : "=r"(r) : "r"(v));
    return r;
}
__device__ __forceinline__ unsigned redux_min_u32(unsigned v)
{
    unsigned r;
    asm("redux.sync.min.u32 %0, %1, 0xffffffff;" : "=r"(r) : "r"(v));
    return r;
}

// ---------------------------------------------------------------------------
// Kernel 2: Viterbi. One CTA/batch, 512 threads (u = tid>>2, quarter = tid&3).
// Full register budget (occupancy 1): chain col in regs, 4-deep pot prefetch
// ring so the global logits load is never on the serial chain.
// Forward stores max values only; history -> g_hist; backtrace (warp 0)
// recomputes argmax per step with transposed chain in smem.
// ---------------------------------------------------------------------------
// Transposed-chain stride: 132 floats = 528 B (16B-aligned rows for float4;
// 132 mod 32 = 4 de-stripes STS conflicts).
#define CHT_LD 132

__global__ __launch_bounds__(512, 1)
void viterbi_kernel(const float* __restrict__ chain,
                    float* __restrict__ out)
{
    extern __shared__ float sm[];
    float* chT   = sm;                 // [128][CHT_LD]
    float* state = sm + UU * CHT_LD;   // [2][128]

    const int tid = threadIdx.x;
    const int b   = blockIdx.x;
    const int u   = tid >> 2;          // 0..127
    const int q   = tid & 3;           // u' chunk [q*32, q*32+32)

    const float* lg = g_logits + (size_t)b * TT * UU;
    float*       hb = g_hist   + (size_t)b * TT * UU;

    // Transposed chain into smem (backtrace)
    for (int i = tid; i < UU * UU; i += 512) {
        const int r = i >> 7, c = i & 127;
        chT[c * CHT_LD + r] = chain[i];
    }

    // chain column for this (u, quarter) in registers
    float creg[32];
    #pragma unroll
    for (int j = 0; j < 32; j++)
        creg[j] = chain[(size_t)(q * 32 + j) * UU + u];

    if (tid < UU)
        state[tid] = lg[tid];

    // pot prefetch ring: pp[i] holds logits for step t = 1+i initially
    float pp[4];
    #pragma unroll
    for (int i = 0; i < 4; i++)
        pp[i] = lg[(size_t)(1 + i) * UU + u];

    __syncthreads();

    int cur = 0;
    for (int t = 1; t < TT; t++) {
        const int slot = (t - 1) & 3;
        const float pot = pp[slot];
        if (t + 4 < TT)
            pp[slot] = lg[(size_t)(t + 4) * UU + u];

        const float* st = state + cur * UU;

        float m0 = -INFINITY, m1 = -INFINITY, m2 = -INFINITY, m3 = -INFINITY;
        #pragma unroll
        for (int j = 0; j < 32; j += 4) {
            const float4 s4 = *reinterpret_cast<const float4*>(&st[q * 32 + j]);
            m0 = fmaxf(m0, s4.x + creg[j + 0]);
            m1 = fmaxf(m1, s4.y + creg[j + 1]);
            m2 = fmaxf(m2, s4.z + creg[j + 2]);
            m3 = fmaxf(m3, s4.w + creg[j + 3]);
        }
        float m = fmaxf(fmaxf(m0, m1), fmaxf(m2, m3));
        m = fmaxf(m, __shfl_xor_sync(0xffffffffu, m, 1));
        m = fmaxf(m, __shfl_xor_sync(0xffffffffu, m, 2));

        const float ns = pot + m;
        if (q == 0)
            state[(cur ^ 1) * UU + u] = ns;   // next-step state (smem)
        else if (q == 1)
            hb[(size_t)t * UU + u] = ns;      // history for backtrace
        cur ^= 1;
        __syncthreads();
    }

    // ---------------- Backtrace: warp 0 only ----------------
    if (tid < 32) {
        const int lane = tid;
        float* o = out + (size_t)b * TT;

        const float4 fs =
            *reinterpret_cast<const float4*>(&state[cur * UU + lane * 4]);
        unsigned k0 = fkey(fs.x), k1 = fkey(fs.y);
        unsigned k2 = fkey(fs.z), k3 = fkey(fs.w);
        unsigned M = redux_max_u32(umax(umax(k0, k1), umax(k2, k3)));
        unsigned idx = 0x7fffffffu;
        if (k3 == M) idx = lane * 4 + 3;
        if (k2 == M) idx = lane * 4 + 2;
        if (k1 == M) idx = lane * 4 + 1;
        if (k0 == M) idx = lane * 4 + 0;
        unsigned tag = redux_min_u32(idx);
        if (lane == 0) o[TT - 1] = (float)tag;

        // state row for step t: t==0 -> logits row 0, else history
        const float* row_next = hb + (size_t)(TT - 2) * UU;
        float4 sb = *reinterpret_cast<const float4*>(&row_next[lane * 4]);
        for (int t = TT - 2; t >= 0; t--) {
            const float4 sv = sb;
            if (t > 0) {
                const float* rp = (t - 1 == 0) ? lg : hb + (size_t)(t - 1) * UU;
                sb = *reinterpret_cast<const float4*>(&rp[lane * 4]);
            }
            const float4 ch = *reinterpret_cast<const float4*>(
                &chT[tag * CHT_LD + lane * 4]);
            k0 = fkey(sv.x + ch.x);
            k1 = fkey(sv.y + ch.y);
            k2 = fkey(sv.z + ch.z);
            k3 = fkey(sv.w + ch.w);
            M = redux_max_u32(umax(umax(k0, k1), umax(k2, k3)));
            idx = 0x7fffffffu;
            if (k3 == M) idx = lane * 4 + 3;
            if (k2 == M) idx = lane * 4 + 2;
            if (k1 == M) idx = lane * 4 + 1;
            if (k0 == M) idx = lane * 4 + 0;
            tag = redux_min_u32(idx);
            if (lane == 0) o[t] = (float)tag;
        }
    }
}

// ---------------------------------------------------------------------------
extern "C" void kernel_launch(void* const* d_in, const int* in_sizes, int n_in,
                              void* d_out, int out_size)
{
    const float* inputs = (const float*)d_in[0];   // (B,T,D)
    const float* kernel = (const float*)d_in[1];   // (D,U)
    const float* bias   = (const float*)d_in[2];   // (U)
    const float* chain  = (const float*)d_in[3];   // (U,U)
    float* out = (float*)d_out;                    // (B,T)

    (void)in_sizes; (void)n_in; (void)out_size;

    gemm_bias_kernel<<<MM / GBM, 256>>>(inputs, kernel, bias);

    const int smem_v = (UU * CHT_LD + 2 * UU) * (int)sizeof(float); // 68608
    cudaFuncSetAttribute(viterbi_kernel,
                         cudaFuncAttributeMaxDynamicSharedMemorySize,
                         smem_v);
    viterbi_kernel<<<BB, 512, smem_v>>>(chain, out);
}

// round 7
// speedup vs baseline: 2.4621x; 2.1340x over previous
#include <cuda_runtime.h>
#include <cuda_bf16.h>
#include <math.h>
#include <stdint.h>

// Problem shapes (fixed)
#define BB 64
#define TT 512
#define DD 1024
#define UU 128
#define MM (BB * TT)

typedef unsigned long long u64;

// Scratch (no cudaMalloc allowed)
__device__ float g_logits[MM * UU];   // GEMM output
__device__ float g_hist[MM * UU];     // viterbi state history (t>=1)

// ---------------------------------------------------------------------------
// Kernel 1: logits = X(M,K) @ W(K,U) + bias  (exact fp32 SIMT GEMM)
// ---------------------------------------------------------------------------
#define GBM 128
#define GBK 16

__global__ __launch_bounds__(256, 2)
void gemm_bias_kernel(const float* __restrict__ A,
                      const float* __restrict__ W,
                      const float* __restrict__ bias)
{
    __shared__ float As[GBK][GBM];
    __shared__ float Bs[GBK][UU];

    const int tid  = threadIdx.x;
    const int row0 = blockIdx.x * GBM;

    const int arow = tid >> 2;
    const int ak   = (tid & 3) * 4;
    const int wk   = tid >> 5;
    const int wcol = (tid & 31) * 4;

    const int tx = tid & 15;
    const int ty = tid >> 4;

    float acc[8][8];
    #pragma unroll
    for (int i = 0; i < 8; i++)
        #pragma unroll
        for (int j = 0; j < 8; j++)
            acc[i][j] = 0.0f;

    for (int k0 = 0; k0 < DD; k0 += GBK) {
        #pragma unroll
        for (int i = 0; i < 2; i++) {
            const float4 v = *reinterpret_cast<const float4*>(
                &A[(size_t)(row0 + arow + i * 64) * DD + k0 + ak]);
            As[ak + 0][arow + i * 64] = v.x;
            As[ak + 1][arow + i * 64] = v.y;
            As[ak + 2][arow + i * 64] = v.z;
            As[ak + 3][arow + i * 64] = v.w;
        }
        #pragma unroll
        for (int i = 0; i < 2; i++) {
            const float4 v = *reinterpret_cast<const float4*>(
                &W[(size_t)(k0 + wk + i * 8) * UU + wcol]);
            *reinterpret_cast<float4*>(&Bs[wk + i * 8][wcol]) = v;
        }
        __syncthreads();

        #pragma unroll
        for (int k = 0; k < GBK; k++) {
            float a[8], b[8];
            *reinterpret_cast<float4*>(&a[0]) =
                *reinterpret_cast<const float4*>(&As[k][ty * 8]);
            *reinterpret_cast<float4*>(&a[4]) =
                *reinterpret_cast<const float4*>(&As[k][ty * 8 + 4]);
            *reinterpret_cast<float4*>(&b[0]) =
                *reinterpret_cast<const float4*>(&Bs[k][tx * 8]);
            *reinterpret_cast<float4*>(&b[4]) =
                *reinterpret_cast<const float4*>(&Bs[k][tx * 8 + 4]);
            #pragma unroll
            for (int i = 0; i < 8; i++)
                #pragma unroll
                for (int j = 0; j < 8; j++)
                    acc[i][j] = fmaf(a[i], b[j], acc[i][j]);
        }
        __syncthreads();
    }

    float bv[8];
    *reinterpret_cast<float4*>(&bv[0]) =
        *reinterpret_cast<const float4*>(&bias[tx * 8]);
    *reinterpret_cast<float4*>(&bv[4]) =
        *reinterpret_cast<const float4*>(&bias[tx * 8 + 4]);

    #pragma unroll
    for (int i = 0; i < 8; i++) {
        const size_t row = (size_t)(row0 + ty * 8 + i);
        float4 o0, o1;
        o0.x = acc[i][0] + bv[0]; o0.y = acc[i][1] + bv[1];
        o0.z = acc[i][2] + bv[2]; o0.w = acc[i][3] + bv[3];
        o1.x = acc[i][4] + bv[4]; o1.y = acc[i][5] + bv[5];
        o1.z = acc[i][6] + bv[6]; o1.w = acc[i][7] + bv[7];
        *reinterpret_cast<float4*>(&g_logits[row * UU + tx * 8])     = o0;
        *reinterpret_cast<float4*>(&g_logits[row * UU + tx * 8 + 4]) = o1;
    }
}

// ---------------------------------------------------------------------------
// ordered-int argmax helpers (exact, first-index tie rule)
// ---------------------------------------------------------------------------
__device__ __forceinline__ unsigned fkey(float f)
{
    const unsigned b = __float_as_uint(f);
    return b ^ ((unsigned)(((int)b) >> 31) | 0x80000000u);
}
__device__ __forceinline__ unsigned redux_max_u32(unsigned v)
{
    unsigned r;
    asm("redux.sync.max.u32 %0, %1, 0xffffffff;" : "=r"(r) : "r"(v));
    return r;
}
__device__ __forceinline__ unsigned redux_min_u32(unsigned v)
{
    unsigned r;
    asm("redux.sync.min.u32 %0, %1, 0xffffffff;" : "=r"(r) : "r"(v));
    return r;
}

// packed fp32 helpers
#define ADD2(d, a, b) \
    asm("add.rn.f32x2 %0, %1, %2;" : "=l"(d) : "l"(a), "l"(b))
#define UNPK2(lo, hi, v) \
    asm("mov.b64 {%0, %1}, %2;" : "=r"(lo), "=r"(hi) : "l"(v))

// ---------------------------------------------------------------------------
// Kernel 2: Viterbi. One CTA/batch, 256 threads: u = tid>>1, half = tid&1.
// Chain column packed (f32x2) in regs; state in smem (double-buffered);
// 4-register prefetch ring (static slots, manual 4x unroll); half-rotated
// LDS access -> conflict-free. Forward stores max values only; backtrace
// (warp 0) recomputes argmax per step.
// ---------------------------------------------------------------------------
#define CHT_LD 132   // 528B rows: 16B-aligned, de-striped STS

__global__ __launch_bounds__(256, 1)
void viterbi_kernel(const float* __restrict__ chain,
                    float* __restrict__ out)
{
    extern __shared__ float sm[];
    float* chT   = sm;                 // [128][CHT_LD]
    float* state = sm + UU * CHT_LD;   // [2][128]

    const int tid  = threadIdx.x;
    const int b    = blockIdx.x;
    const int u    = tid >> 1;         // 0..127
    const int half = tid & 1;          // u' block [half*64, half*64+64)
    const int base = half * 64;
    const int rot  = 16 * half;        // bank de-rotation offset

    const float* lg = g_logits + (size_t)b * TT * UU;
    float*       hb = g_hist   + (size_t)b * TT * UU;

    // Transposed chain into smem (backtrace)
    for (int i = tid; i < UU * UU; i += 256) {
        const int r = i >> 7, c = i & 127;
        chT[c * CHT_LD + r] = chain[i];
    }

    // chain column, in rotated order, packed as f32x2 pairs
    u64 cpk[32];
    #pragma unroll
    for (int k = 0; k < 32; k++) {
        const int e0 = base + ((2 * k + rot) & 63);
        const float c0 = chain[(size_t)e0 * UU + u];
        const float c1 = chain[(size_t)(e0 + 1) * UU + u];
        asm("mov.b64 %0, {%1, %2};" : "=l"(cpk[k])
            : "r"(__float_as_uint(c0)), "r"(__float_as_uint(c1)));
    }

    if (tid < UU)
        state[tid] = lg[tid];

    // prefetch ring: p0..p3 hold logits rows t=1..4 for this u
    float p0 = lg[1 * UU + u];
    float p1 = lg[2 * UU + u];
    float p2 = lg[3 * UU + u];
    float p3 = lg[4 * UU + u];
    const float* pref_ptr = lg + (size_t)5 * UU + u;   // row t+4 for t=1
    float*       hist_ptr = hb + (size_t)1 * UU + u;

    __syncthreads();

    int cur = 0;

#define VSTEP(T, PREG)                                                       \
    {                                                                        \
        const float pot = PREG;                                              \
        if ((T) + 4 < TT) PREG = *pref_ptr;                                  \
        pref_ptr += UU;                                                      \
        const float* st = state + cur * UU;                                  \
        float m0 = -INFINITY, m1 = -INFINITY, m2 = -INFINITY, m3 = -INFINITY;\
        _Pragma("unroll")                                                    \
        for (int j = 0; j < 64; j += 4) {                                    \
            const int e = base + ((j + rot) & 63);                           \
            const ulonglong2 s2 =                                            \
                *reinterpret_cast<const ulonglong2*>(&st[e]);                \
            u64 r0, r1;                                                      \
            ADD2(r0, s2.x, cpk[j >> 1]);                                     \
            ADD2(r1, s2.y, cpk[(j >> 1) + 1]);                               \
            unsigned x0, x1, x2, x3;                                         \
            UNPK2(x0, x1, r0);                                               \
            UNPK2(x2, x3, r1);                                               \
            m0 = fmaxf(m0, __uint_as_float(x0));                             \
            m1 = fmaxf(m1, __uint_as_float(x1));                             \
            m2 = fmaxf(m2, __uint_as_float(x2));                             \
            m3 = fmaxf(m3, __uint_as_float(x3));                             \
        }                                                                    \
        float m = fmaxf(fmaxf(m0, m1), fmaxf(m2, m3));                       \
        m = fmaxf(m, __shfl_xor_sync(0xffffffffu, m, 1));                    \
        const float ns = pot + m;                                            \
        if (half == 0)                                                       \
            state[(cur ^ 1) * UU + u] = ns;                                  \
        else                                                                 \
            *hist_ptr = ns;                                                  \
        hist_ptr += UU;                                                      \
        cur ^= 1;                                                            \
        __syncthreads();                                                     \
    }

    int t = 1;
    for (; t + 3 < TT; t += 4) {
        VSTEP(t + 0, p0);
        VSTEP(t + 1, p1);
        VSTEP(t + 2, p2);
        VSTEP(t + 3, p3);
    }
    // tail: t = 509, 510, 511
    VSTEP(t + 0, p0);
    VSTEP(t + 1, p1);
    VSTEP(t + 2, p2);
#undef VSTEP

    // ---------------- Backtrace: warp 0 only ----------------
    if (tid < 32) {
        const int lane = tid;
        float* o = out + (size_t)b * TT;

        const float4 fs =
            *reinterpret_cast<const float4*>(&state[cur * UU + lane * 4]);
        unsigned k0 = fkey(fs.x), k1 = fkey(fs.y);
        unsigned k2 = fkey(fs.z), k3 = fkey(fs.w);
        unsigned M = redux_max_u32(umax(umax(k0, k1), umax(k2, k3)));
        unsigned idx = 0x7fffffffu;
        if (k3 == M) idx = lane * 4 + 3;
        if (k2 == M) idx = lane * 4 + 2;
        if (k1 == M) idx = lane * 4 + 1;
        if (k0 == M) idx = lane * 4 + 0;
        unsigned tag = redux_min_u32(idx);
        if (lane == 0) o[TT - 1] = (float)tag;

        // state row for step t: t==0 -> logits row 0, else history
        const float* row_next = hb + (size_t)(TT - 2) * UU;
        float4 sb = *reinterpret_cast<const float4*>(&row_next[lane * 4]);
        for (int tt = TT - 2; tt >= 0; tt--) {
            const float4 sv = sb;
            if (tt > 0) {
                const float* rp =
                    (tt - 1 == 0) ? lg : hb + (size_t)(tt - 1) * UU;
                sb = *reinterpret_cast<const float4*>(&rp[lane * 4]);
            }
            const float4 ch = *reinterpret_cast<const float4*>(
                &chT[tag * CHT_LD + lane * 4]);
            k0 = fkey(sv.x + ch.x);
            k1 = fkey(sv.y + ch.y);
            k2 = fkey(sv.z + ch.z);
            k3 = fkey(sv.w + ch.w);
            M = redux_max_u32(umax(umax(k0, k1), umax(k2, k3)));
            idx = 0x7fffffffu;
            if (k3 == M) idx = lane * 4 + 3;
            if (k2 == M) idx = lane * 4 + 2;
            if (k1 == M) idx = lane * 4 + 1;
            if (k0 == M) idx = lane * 4 + 0;
            tag = redux_min_u32(idx);
            if (lane == 0) o[tt] = (float)tag;
        }
    }
}

// ---------------------------------------------------------------------------
extern "C" void kernel_launch(void* const* d_in, const int* in_sizes, int n_in,
                              void* d_out, int out_size)
{
    const float* inputs = (const float*)d_in[0];   // (B,T,D)
    const float* kernel = (const float*)d_in[1];   // (D,U)
    const float* bias   = (const float*)d_in[2];   // (U)
    const float* chain  = (const float*)d_in[3];   // (U,U)
    float* out = (float*)d_out;                    // (B,T)

    (void)in_sizes; (void)n_in; (void)out_size;

    gemm_bias_kernel<<<MM / GBM, 256>>>(inputs, kernel, bias);

    const int smem_v = (UU * CHT_LD + 2 * UU) * (int)sizeof(float); // 68608
    cudaFuncSetAttribute(viterbi_kernel,
                         cudaFuncAttributeMaxDynamicSharedMemorySize,
                         smem_v);
    viterbi_kernel<<<BB, 256, smem_v>>>(chain, out);
}

// round 8
// speedup vs baseline: 2.5291x; 1.0272x over previous
#include <cuda_runtime.h>
#include <cuda_bf16.h>
#include <math.h>
#include <stdint.h>

// Problem shapes (fixed)
#define BB 64
#define TT 512
#define DD 1024
#define UU 128
#define MM (BB * TT)

typedef unsigned long long u64;

// Scratch (no cudaMalloc allowed)
__device__ float g_logits[MM * UU];   // GEMM output
__device__ float g_hist[MM * UU];     // viterbi state history (t>=1)

// ---------------------------------------------------------------------------
// Kernel 1: logits = X(M,K) @ W(K,U) + bias  (exact fp32, double-buffered)
// Tile BM=128, BN=128, BK=16; 256 threads; 8x8 accum; regs<->smem pipeline,
// one __syncthreads per k-iter.
// ---------------------------------------------------------------------------
#define GBM 128
#define GBK 16

__global__ __launch_bounds__(256, 2)
void gemm_bias_kernel(const float* __restrict__ A,
                      const float* __restrict__ W,
                      const float* __restrict__ bias)
{
    __shared__ float As[2][GBK][GBM];   // transposed: As[s][k][m]
    __shared__ float Bs[2][GBK][UU];    // Bs[s][k][n]

    const int tid  = threadIdx.x;
    const int row0 = blockIdx.x * GBM;

    const int arow = tid >> 2;          // 0..63
    const int ak   = (tid & 3) * 4;     // 0,4,8,12
    const int wk   = tid >> 5;          // 0..7
    const int wcol = (tid & 31) * 4;    // 0..124

    const int tx = tid & 15;
    const int ty = tid >> 4;

    float acc[8][8];
    #pragma unroll
    for (int i = 0; i < 8; i++)
        #pragma unroll
        for (int j = 0; j < 8; j++)
            acc[i][j] = 0.0f;

    const float* A0 = A + (size_t)(row0 + arow) * DD + ak;
    const float* A1 = A + (size_t)(row0 + arow + 64) * DD + ak;

    // ---- prologue: load k0=0 into regs, store stage 0 ----
    float4 ra0 = *reinterpret_cast<const float4*>(A0);
    float4 ra1 = *reinterpret_cast<const float4*>(A1);
    float4 rw0 = *reinterpret_cast<const float4*>(&W[(size_t)wk * UU + wcol]);
    float4 rw1 = *reinterpret_cast<const float4*>(&W[(size_t)(wk + 8) * UU + wcol]);

    As[0][ak + 0][arow] = ra0.x; As[0][ak + 1][arow] = ra0.y;
    As[0][ak + 2][arow] = ra0.z; As[0][ak + 3][arow] = ra0.w;
    As[0][ak + 0][arow + 64] = ra1.x; As[0][ak + 1][arow + 64] = ra1.y;
    As[0][ak + 2][arow + 64] = ra1.z; As[0][ak + 3][arow + 64] = ra1.w;
    *reinterpret_cast<float4*>(&Bs[0][wk][wcol])     = rw0;
    *reinterpret_cast<float4*>(&Bs[0][wk + 8][wcol]) = rw1;
    __syncthreads();

    int st = 0;
    for (int k0 = GBK; k0 <= DD; k0 += GBK) {
        const bool more = (k0 < DD);
        if (more) {
            ra0 = *reinterpret_cast<const float4*>(A0 + k0);
            ra1 = *reinterpret_cast<const float4*>(A1 + k0);
            rw0 = *reinterpret_cast<const float4*>(&W[(size_t)(k0 + wk) * UU + wcol]);
            rw1 = *reinterpret_cast<const float4*>(&W[(size_t)(k0 + wk + 8) * UU + wcol]);
        }

        // compute current stage
        #pragma unroll
        for (int k = 0; k < GBK; k++) {
            float a[8], b[8];
            *reinterpret_cast<float4*>(&a[0]) =
                *reinterpret_cast<const float4*>(&As[st][k][ty * 8]);
            *reinterpret_cast<float4*>(&a[4]) =
                *reinterpret_cast<const float4*>(&As[st][k][ty * 8 + 4]);
            *reinterpret_cast<float4*>(&b[0]) =
                *reinterpret_cast<const float4*>(&Bs[st][k][tx * 8]);
            *reinterpret_cast<float4*>(&b[4]) =
                *reinterpret_cast<const float4*>(&Bs[st][k][tx * 8 + 4]);
            #pragma unroll
            for (int i = 0; i < 8; i++)
                #pragma unroll
                for (int j = 0; j < 8; j++)
                    acc[i][j] = fmaf(a[i], b[j], acc[i][j]);
        }

        if (more) {
            const int ns = st ^ 1;
            As[ns][ak + 0][arow] = ra0.x; As[ns][ak + 1][arow] = ra0.y;
            As[ns][ak + 2][arow] = ra0.z; As[ns][ak + 3][arow] = ra0.w;
            As[ns][ak + 0][arow + 64] = ra1.x; As[ns][ak + 1][arow + 64] = ra1.y;
            As[ns][ak + 2][arow + 64] = ra1.z; As[ns][ak + 3][arow + 64] = ra1.w;
            *reinterpret_cast<float4*>(&Bs[ns][wk][wcol])     = rw0;
            *reinterpret_cast<float4*>(&Bs[ns][wk + 8][wcol]) = rw1;
            __syncthreads();
            st = ns;
        }
    }

    float bv[8];
    *reinterpret_cast<float4*>(&bv[0]) =
        *reinterpret_cast<const float4*>(&bias[tx * 8]);
    *reinterpret_cast<float4*>(&bv[4]) =
        *reinterpret_cast<const float4*>(&bias[tx * 8 + 4]);

    #pragma unroll
    for (int i = 0; i < 8; i++) {
        const size_t row = (size_t)(row0 + ty * 8 + i);
        float4 o0, o1;
        o0.x = acc[i][0] + bv[0]; o0.y = acc[i][1] + bv[1];
        o0.z = acc[i][2] + bv[2]; o0.w = acc[i][3] + bv[3];
        o1.x = acc[i][4] + bv[4]; o1.y = acc[i][5] + bv[5];
        o1.z = acc[i][6] + bv[6]; o1.w = acc[i][7] + bv[7];
        *reinterpret_cast<float4*>(&g_logits[row * UU + tx * 8])     = o0;
        *reinterpret_cast<float4*>(&g_logits[row * UU + tx * 8 + 4]) = o1;
    }
}

// ---------------------------------------------------------------------------
// ordered-int argmax helpers (exact, first-index tie rule)
// ---------------------------------------------------------------------------
__device__ __forceinline__ unsigned fkey(float f)
{
    const unsigned b = __float_as_uint(f);
    return b ^ ((unsigned)(((int)b) >> 31) | 0x80000000u);
}
__device__ __forceinline__ unsigned redux_max_u32(unsigned v)
{
    unsigned r;
    asm("redux.sync.max.u32 %0, %1, 0xffffffff;" : "=r"(r) : "r"(v));
    return r;
}
__device__ __forceinline__ unsigned redux_min_u32(unsigned v)
{
    unsigned r;
    asm("redux.sync.min.u32 %0, %1, 0xffffffff;" : "=r"(r) : "r"(v));
    return r;
}

// packed fp32 helpers
#define ADD2(d, a, b) \
    asm("add.rn.f32x2 %0, %1, %2;" : "=l"(d) : "l"(a), "l"(b))
#define UNPK2(lo, hi, v) \
    asm("mov.b64 {%0, %1}, %2;" : "=r"(lo), "=r"(hi) : "l"(v))

// ---------------------------------------------------------------------------
// Kernel 2: Viterbi. One CTA/batch, 256 threads: u = tid>>1, half = tid&1.
// 8 max accumulators (chain depth 8); chain column packed in regs; rotated
// conflict-free LDS; 4-register static prefetch ring.
// ---------------------------------------------------------------------------
#define CHT_LD 132   // 528B rows: 16B-aligned, de-striped STS

__global__ __launch_bounds__(256, 1)
void viterbi_kernel(const float* __restrict__ chain,
                    float* __restrict__ out)
{
    extern __shared__ float sm[];
    float* chT   = sm;                 // [128][CHT_LD]
    float* state = sm + UU * CHT_LD;   // [2][128]

    const int tid  = threadIdx.x;
    const int b    = blockIdx.x;
    const int u    = tid >> 1;         // 0..127
    const int half = tid & 1;          // u' block [half*64, half*64+64)
    const int base = half * 64;
    const int rot  = 16 * half;        // bank de-rotation offset

    const float* lg = g_logits + (size_t)b * TT * UU;
    float*       hb = g_hist   + (size_t)b * TT * UU;

    // Transposed chain into smem (backtrace)
    for (int i = tid; i < UU * UU; i += 256) {
        const int r = i >> 7, c = i & 127;
        chT[c * CHT_LD + r] = chain[i];
    }

    // chain column, in rotated order, packed as f32x2 pairs
    u64 cpk[32];
    #pragma unroll
    for (int k = 0; k < 32; k++) {
        const int e0 = base + ((2 * k + rot) & 63);
        const float c0 = chain[(size_t)e0 * UU + u];
        const float c1 = chain[(size_t)(e0 + 1) * UU + u];
        asm("mov.b64 %0, {%1, %2};" : "=l"(cpk[k])
            : "r"(__float_as_uint(c0)), "r"(__float_as_uint(c1)));
    }

    if (tid < UU)
        state[tid] = lg[tid];

    // prefetch ring: p0..p3 hold logits rows t=1..4 for this u
    float p0 = lg[1 * UU + u];
    float p1 = lg[2 * UU + u];
    float p2 = lg[3 * UU + u];
    float p3 = lg[4 * UU + u];
    const float* pref_ptr = lg + (size_t)5 * UU + u;
    float*       hist_ptr = hb + (size_t)1 * UU + u;

    __syncthreads();

    int cur = 0;

#define VSTEP(T, PREG)                                                       \
    {                                                                        \
        const float pot = PREG;                                              \
        if ((T) + 4 < TT) PREG = *pref_ptr;                                  \
        pref_ptr += UU;                                                      \
        const float* st = state + cur * UU;                                  \
        float m0 = -INFINITY, m1 = -INFINITY, m2 = -INFINITY, m3 = -INFINITY;\
        float m4 = -INFINITY, m5 = -INFINITY, m6 = -INFINITY, m7 = -INFINITY;\
        _Pragma("unroll")                                                    \
        for (int j = 0; j < 64; j += 8) {                                    \
            const int e = base + ((j + rot) & 63);                           \
            const ulonglong2 sA =                                            \
                *reinterpret_cast<const ulonglong2*>(&st[e]);                \
            const ulonglong2 sB =                                            \
                *reinterpret_cast<const ulonglong2*>(&st[e + 4]);            \
            u64 r0, r1, r2, r3;                                              \
            ADD2(r0, sA.x, cpk[(j >> 1) + 0]);                               \
            ADD2(r1, sA.y, cpk[(j >> 1) + 1]);                               \
            ADD2(r2, sB.x, cpk[(j >> 1) + 2]);                               \
            ADD2(r3, sB.y, cpk[(j >> 1) + 3]);                               \
            unsigned x0, x1, x2, x3, x4, x5, x6, x7;                         \
            UNPK2(x0, x1, r0);                                               \
            UNPK2(x2, x3, r1);                                               \
            UNPK2(x4, x5, r2);                                               \
            UNPK2(x6, x7, r3);                                               \
            m0 = fmaxf(m0, __uint_as_float(x0));                             \
            m1 = fmaxf(m1, __uint_as_float(x1));                             \
            m2 = fmaxf(m2, __uint_as_float(x2));                             \
            m3 = fmaxf(m3, __uint_as_float(x3));                             \
            m4 = fmaxf(m4, __uint_as_float(x4));                             \
            m5 = fmaxf(m5, __uint_as_float(x5));                             \
            m6 = fmaxf(m6, __uint_as_float(x6));                             \
            m7 = fmaxf(m7, __uint_as_float(x7));                             \
        }                                                                    \
        float m = fmaxf(fmaxf(fmaxf(m0, m1), fmaxf(m2, m3)),                 \
                        fmaxf(fmaxf(m4, m5), fmaxf(m6, m7)));                \
        m = fmaxf(m, __shfl_xor_sync(0xffffffffu, m, 1));                    \
        const float ns = pot + m;                                            \
        if (half == 0)                                                       \
            state[(cur ^ 1) * UU + u] = ns;                                  \
        else                                                                 \
            *hist_ptr = ns;                                                  \
        hist_ptr += UU;                                                      \
        cur ^= 1;                                                            \
        __syncthreads();                                                     \
    }

    int t = 1;
    for (; t + 3 < TT; t += 4) {
        VSTEP(t + 0, p0);
        VSTEP(t + 1, p1);
        VSTEP(t + 2, p2);
        VSTEP(t + 3, p3);
    }
    // tail: t = 509, 510, 511
    VSTEP(t + 0, p0);
    VSTEP(t + 1, p1);
    VSTEP(t + 2, p2);
#undef VSTEP

    // ---------------- Backtrace: warp 0 only ----------------
    if (tid < 32) {
        const int lane = tid;
        float* o = out + (size_t)b * TT;

        const float4 fs =
            *reinterpret_cast<const float4*>(&state[cur * UU + lane * 4]);
        unsigned k0 = fkey(fs.x), k1 = fkey(fs.y);
        unsigned k2 = fkey(fs.z), k3 = fkey(fs.w);
        unsigned M = redux_max_u32(umax(umax(k0, k1), umax(k2, k3)));
        unsigned idx = 0x7fffffffu;
        if (k3 == M) idx = lane * 4 + 3;
        if (k2 == M) idx = lane * 4 + 2;
        if (k1 == M) idx = lane * 4 + 1;
        if (k0 == M) idx = lane * 4 + 0;
        unsigned tag = redux_min_u32(idx);
        if (lane == 0) o[TT - 1] = (float)tag;

        const float* row_next = hb + (size_t)(TT - 2) * UU;
        float4 sb = *reinterpret_cast<const float4*>(&row_next[lane * 4]);
        for (int tt = TT - 2; tt >= 0; tt--) {
            const float4 sv = sb;
            if (tt > 0) {
                const float* rp =
                    (tt - 1 == 0) ? lg : hb + (size_t)(tt - 1) * UU;
                sb = *reinterpret_cast<const float4*>(&rp[lane * 4]);
            }
            const float4 ch = *reinterpret_cast<const float4*>(
                &chT[tag * CHT_LD + lane * 4]);
            k0 = fkey(sv.x + ch.x);
            k1 = fkey(sv.y + ch.y);
            k2 = fkey(sv.z + ch.z);
            k3 = fkey(sv.w + ch.w);
            M = redux_max_u32(umax(umax(k0, k1), umax(k2, k3)));
            idx = 0x7fffffffu;
            if (k3 == M) idx = lane * 4 + 3;
            if (k2 == M) idx = lane * 4 + 2;
            if (k1 == M) idx = lane * 4 + 1;
            if (k0 == M) idx = lane * 4 + 0;
            tag = redux_min_u32(idx);
            if (lane == 0) o[tt] = (float)tag;
        }
    }
}

// ---------------------------------------------------------------------------
extern "C" void kernel_launch(void* const* d_in, const int* in_sizes, int n_in,
                              void* d_out, int out_size)
{
    const float* inputs = (const float*)d_in[0];   // (B,T,D)
    const float* kernel = (const float*)d_in[1];   // (D,U)
    const float* bias   = (const float*)d_in[2];   // (U)
    const float* chain  = (const float*)d_in[3];   // (U,U)
    float* out = (float*)d_out;                    // (B,T)

    (void)in_sizes; (void)n_in; (void)out_size;

    gemm_bias_kernel<<<MM / GBM, 256>>>(inputs, kernel, bias);

    const int smem_v = (UU * CHT_LD + 2 * UU) * (int)sizeof(float); // 68608
    cudaFuncSetAttribute(viterbi_kernel,
                         cudaFuncAttributeMaxDynamicSharedMemorySize,
                         smem_v);
    viterbi_kernel<<<BB, 256, smem_v>>>(chain, out);
}